// round 2
// baseline (speedup 1.0000x reference)
#include <cuda_runtime.h>

#define NB   512
#define NT   1000
#define NC   64
#define NH   128
#define NTDA 150
#define NCLS 4

// Scratch (no cudaMalloc allowed): classifier hidden + BN stats
__device__ float g_h[NB * NH];
__device__ float g_mean[NH];
__device__ float g_rstd[NH];

typedef unsigned long long u64;

__device__ __forceinline__ u64 fma2(u64 a, u64 b, u64 c) {
    u64 d;
    asm("fma.rn.f32x2 %0, %1, %2, %3;" : "=l"(d) : "l"(a), "l"(b), "l"(c));
    return d;
}
__device__ __forceinline__ u64 add2(u64 a, u64 b) {
    u64 d;
    asm("add.rn.f32x2 %0, %1, %2;" : "=l"(d) : "l"(a), "l"(b));
    return d;
}
__device__ __forceinline__ float2 unpack2(u64 a) {
    float2 f;
    asm("mov.b64 {%0, %1}, %2;" : "=f"(f.x), "=f"(f.y) : "l"(a));
    return f;
}

// ---------------------------------------------------------------------------
// Kernel 1: fused input-current GEMM + LIF scan.
// Grid: NB*2 blocks of 64 threads. Block bb handles batch b = bb>>1,
// h-range [(bb&1)*64, +64). Thread = one h; its W_fc row lives in 32 packed
// f32x2 registers. x[b,t,:] streams through double-buffered smem, 8 t/group.
// ---------------------------------------------------------------------------
__global__ void __launch_bounds__(64, 6) snn_kernel(
    const float* __restrict__ x, const float* __restrict__ Wfc,
    const float* __restrict__ bfc, float* __restrict__ counts_out)
{
    __shared__ __align__(16) float sbuf[2][8 * NC];  // 2 x 512 floats

    const int bb  = blockIdx.x;
    const int b   = bb >> 1;
    const int h   = ((bb & 1) << 6) + threadIdx.x;
    const int tid = threadIdx.x;

    // W_fc row h as 32 packed f32x2 (adjacent floats alias a u64 directly)
    u64 wq[32];
    const u64* wp = (const u64*)(Wfc + h * NC);
#pragma unroll
    for (int j = 0; j < 32; j++) wq[j] = wp[j];
    const float bias = bfc[h];

    float mem = 0.0f, cnt = 0.0f;

    const float4* xb = (const float4*)(x + (size_t)b * NT * NC);
    // Prologue: group 0 (512 floats = 128 float4; 64 threads x 2 float4)
    {
        float4 v0 = xb[2 * tid];
        float4 v1 = xb[2 * tid + 1];
        ((float4*)sbuf[0])[2 * tid]     = v0;
        ((float4*)sbuf[0])[2 * tid + 1] = v1;
    }
    __syncthreads();

    for (int g = 0; g < 125; ++g) {
        float4 n0, n1;
        if (g < 124) {
            n0 = xb[(g + 1) * 128 + 2 * tid];
            n1 = xb[(g + 1) * 128 + 2 * tid + 1];
        }
        const u64* xs = (const u64*)sbuf[g & 1];
#pragma unroll
        for (int tt = 0; tt < 8; ++tt) {
            u64 a0 = 0ull, a1 = 0ull, a2 = 0ull, a3 = 0ull;
            const ulonglong2* xv = (const ulonglong2*)(xs + tt * 32);
#pragma unroll
            for (int j = 0; j < 16; j += 2) {
                ulonglong2 p = xv[j];       // 4 x-floats (broadcast LDS.128)
                a0 = fma2(p.x, wq[2 * j],     a0);
                a1 = fma2(p.y, wq[2 * j + 1], a1);
                ulonglong2 q = xv[j + 1];
                a2 = fma2(q.x, wq[2 * j + 2], a2);
                a3 = fma2(q.y, wq[2 * j + 3], a3);
            }
            float2 f = unpack2(add2(add2(a0, a2), add2(a1, a3)));
            float cur = f.x + f.y + bias;
            // LIF: mem = 0.9*mem + cur; spike if mem >= 1; reset to 0
            mem = fmaf(mem, 0.9f, cur);
            if (mem >= 1.0f) { cnt += 1.0f; mem = 0.0f; }
        }
        if (g < 124) {
            float4* d = (float4*)sbuf[(g + 1) & 1];
            d[2 * tid]     = n0;
            d[2 * tid + 1] = n1;
        }
        __syncthreads();
    }

    counts_out[b * NH + h] = cnt;
}

// ---------------------------------------------------------------------------
// Kernel 2: tda MLP + fused-feature classifier layer 1 (pre-BN h rows)
// ---------------------------------------------------------------------------
__global__ void __launch_bounds__(128) head_kernel(
    const float* __restrict__ tda,
    const float* __restrict__ Wt1, const float* __restrict__ bt1,
    const float* __restrict__ Wt2, const float* __restrict__ bt2,
    const float* __restrict__ Wc1, const float* __restrict__ bc1,
    const float* __restrict__ counts)
{
    __shared__ float s_tda[NTDA];
    __shared__ float s_h1[64];
    __shared__ float s_h2[64];
    __shared__ float s_fr[NH];

    const int b = blockIdx.x, tid = threadIdx.x;

    for (int i = tid; i < NTDA; i += 128) s_tda[i] = tda[b * NTDA + i];
    s_fr[tid] = counts[b * NH + tid] * (1.0f / (float)NT);
    __syncthreads();

    if (tid < 64) {
        float a = bt1[tid];
        const float* w = Wt1 + tid * NTDA;
#pragma unroll 5
        for (int c = 0; c < NTDA; c++) a = fmaf(w[c], s_tda[c], a);
        s_h1[tid] = fmaxf(a, 0.0f);
    }
    __syncthreads();

    if (tid < 64) {
        float a = bt2[tid];
        const float* w = Wt2 + tid * 64;
#pragma unroll 8
        for (int c = 0; c < 64; c++) a = fmaf(w[c], s_h1[c], a);
        s_h2[tid] = fmaxf(a, 0.0f);
    }
    __syncthreads();

    // fused = [firing_rate(128), tda_out(64)];  h = fused @ W_c1^T + b_c1
    float a = bc1[tid];
    const float* w = Wc1 + tid * (NH + 64);
#pragma unroll 8
    for (int c = 0; c < NH; c++) a = fmaf(w[c], s_fr[c], a);
#pragma unroll 8
    for (int c = 0; c < 64; c++) a = fmaf(w[NH + c], s_h2[c], a);
    g_h[b * NH + tid] = a;
}

// ---------------------------------------------------------------------------
// Kernel 3: BatchNorm batch statistics (two-pass, biased variance like jnp.var)
// One block per feature column.
// ---------------------------------------------------------------------------
__global__ void __launch_bounds__(256) bn_stats_kernel()
{
    const int j = blockIdx.x, tid = threadIdx.x;
    __shared__ float red[256];
    __shared__ float m_sh;

    float v1 = g_h[tid * NH + j];
    float v2 = g_h[(tid + 256) * NH + j];

    red[tid] = v1 + v2;
    __syncthreads();
    for (int o = 128; o > 0; o >>= 1) {
        if (tid < o) red[tid] += red[tid + o];
        __syncthreads();
    }
    if (tid == 0) m_sh = red[0] * (1.0f / (float)NB);
    __syncthreads();

    const float m = m_sh;
    float d1 = v1 - m, d2 = v2 - m;
    red[tid] = d1 * d1 + d2 * d2;
    __syncthreads();
    for (int o = 128; o > 0; o >>= 1) {
        if (tid < o) red[tid] += red[tid + o];
        __syncthreads();
    }
    if (tid == 0) {
        g_mean[j] = m;
        g_rstd[j] = rsqrtf(red[0] * (1.0f / (float)NB) + 1e-5f);
    }
}

// ---------------------------------------------------------------------------
// Kernel 4: BN apply + ReLU + final Linear(128 -> 4)
// ---------------------------------------------------------------------------
__global__ void __launch_bounds__(128) out_kernel(
    const float* __restrict__ gamma, const float* __restrict__ beta,
    const float* __restrict__ Wc2, const float* __restrict__ bc2,
    float* __restrict__ out)
{
    __shared__ float sv[NH];
    const int b = blockIdx.x, tid = threadIdx.x;

    float v = (g_h[b * NH + tid] - g_mean[tid]) * g_rstd[tid] * gamma[tid] + beta[tid];
    sv[tid] = fmaxf(v, 0.0f);
    __syncthreads();

    const int w = tid >> 5, l = tid & 31;  // 4 warps -> 4 output classes
    const float* wr = Wc2 + w * NH;
    float p = sv[l] * wr[l] + sv[l + 32] * wr[l + 32]
            + sv[l + 64] * wr[l + 64] + sv[l + 96] * wr[l + 96];
#pragma unroll
    for (int o = 16; o > 0; o >>= 1) p += __shfl_down_sync(0xffffffffu, p, o);
    if (l == 0) out[b * NCLS + w] = p + bc2[w];
}

// ---------------------------------------------------------------------------
extern "C" void kernel_launch(void* const* d_in, const int* in_sizes, int n_in,
                              void* d_out, int out_size)
{
    const float* x     = (const float*)d_in[0];   // [512,1000,64]
    const float* tda   = (const float*)d_in[1];   // [512,150]
    const float* Wfc   = (const float*)d_in[2];   // [128,64]
    const float* bfc   = (const float*)d_in[3];   // [128]
    const float* Wt1   = (const float*)d_in[4];   // [64,150]
    const float* bt1   = (const float*)d_in[5];   // [64]
    const float* Wt2   = (const float*)d_in[6];   // [64,64]
    const float* bt2   = (const float*)d_in[7];   // [64]
    const float* Wc1   = (const float*)d_in[8];   // [128,192]
    const float* bc1   = (const float*)d_in[9];   // [128]
    const float* gamma = (const float*)d_in[10];  // [128]
    const float* beta  = (const float*)d_in[11];  // [128]
    const float* Wc2   = (const float*)d_in[12];  // [4,128]
    const float* bc2   = (const float*)d_in[13];  // [4]

    float* out    = (float*)d_out;        // first 512*4 = logits
    float* counts = out + NB * NCLS;      // next 512*128 = spike_counts

    snn_kernel<<<NB * 2, 64>>>(x, Wfc, bfc, counts);
    head_kernel<<<NB, 128>>>(tda, Wt1, bt1, Wt2, bt2, Wc1, bc1, counts);
    bn_stats_kernel<<<NH, 256>>>();
    out_kernel<<<NB, 128>>>(gamma, beta, Wc2, bc2, out);
}

// round 9
// speedup vs baseline: 1.1366x; 1.1366x over previous
#include <cuda_runtime.h>

#define NB   512
#define NT   1000
#define NC   64
#define NH   128
#define NTDA 150
#define NCLS 4

#define GRP_T 40            // timesteps per smem group
#define NGRP  25            // 25 * 40 = 1000
#define XROW  72            // padded floats per x row in smem

// Scratch (no cudaMalloc allowed): classifier hidden + BN stats
__device__ float g_h[NB * NH];
__device__ float g_mean[NH];
__device__ float g_rstd[NH];

typedef unsigned long long u64;

__device__ __forceinline__ u64 fma2(u64 a, u64 b, u64 c) {
    u64 d;
    asm("fma.rn.f32x2 %0, %1, %2, %3;" : "=l"(d) : "l"(a), "l"(b), "l"(c));
    return d;
}
__device__ __forceinline__ u64 add2(u64 a, u64 b) {
    u64 d;
    asm("add.rn.f32x2 %0, %1, %2;" : "=l"(d) : "l"(a), "l"(b));
    return d;
}
__device__ __forceinline__ float2 unpack2(u64 a) {
    float2 f;
    asm("mov.b64 {%0, %1}, %2;" : "=f"(f.x), "=f"(f.y) : "l"(a));
    return f;
}
__device__ __forceinline__ void cp16(void* dst_smem, const void* src) {
    unsigned d = (unsigned)__cvta_generic_to_shared(dst_smem);
    asm volatile("cp.async.cg.shared.global [%0], [%1], 16;" :: "r"(d), "l"(src));
}

// ---------------------------------------------------------------------------
// Kernel 1: fused input-current GEMM + LIF scan.
// Grid: NB*2 blocks of 128 threads. Block bb: batch b = bb>>1, h-range
// [(bb&1)*64, +64). Thread pair (2*h_loc, 2*h_loc+1) splits the C=64 dot
// product in half (channels [0,32) / [32,64)); partials combine with one
// shfl_xor. x streams through a cp.async double-buffered smem tile,
// 40 timesteps per group.
// ---------------------------------------------------------------------------
__global__ void __launch_bounds__(128, 7) snn_kernel(
    const float* __restrict__ x, const float* __restrict__ Wfc,
    const float* __restrict__ bfc, float* __restrict__ counts_out)
{
    __shared__ __align__(16) float sbuf[2][GRP_T * XROW];  // 2 x 11520 B

    const int bb    = blockIdx.x;
    const int b     = bb >> 1;
    const int tid   = threadIdx.x;
    const int h_loc = tid >> 1;
    const int chalf = tid & 1;
    const int h     = ((bb & 1) << 6) + h_loc;

    // This thread's 32-channel half of W_fc row h, packed as 16 f32x2
    u64 wq[16];
    const u64* wp = (const u64*)(Wfc + h * NC) + chalf * 16;
#pragma unroll
    for (int j = 0; j < 16; j++) wq[j] = wp[j];
    // Bias folded into accumulator init (only even lane of the pair carries it)
    const u64 bias_init = chalf ? 0ull : (u64)__float_as_uint(bfc[h]);

    const char* xg = (const char*)(x + (size_t)b * NT * NC);

    // Async load of group g into buf: 40 rows x 64 floats, rows padded to 72.
    // 640 16B-pieces; 128 threads x 5 pieces, fully coalesced in gmem.
    auto load_group = [&](int g, float* buf) {
        const char* src = xg + (size_t)g * GRP_T * NC * 4;
#pragma unroll
        for (int k = 0; k < 5; k++) {
            int p = tid + (k << 7);          // 0..639
            int t_loc = p >> 4;              // 16 pieces per 64-float row
            int c4 = p & 15;
            cp16(buf + t_loc * XROW + (c4 << 2), src + p * 16);
        }
        asm volatile("cp.async.commit_group;");
    };

    load_group(0, sbuf[0]);
    load_group(1, sbuf[1]);

    float mem = 0.0f, cnt = 0.0f;

    for (int g = 0; g < NGRP; ++g) {
        if (g < NGRP - 1) asm volatile("cp.async.wait_group 1;");
        else              asm volatile("cp.async.wait_group 0;");
        __syncthreads();

        const float* buf = sbuf[g & 1];
#pragma unroll 8
        for (int tt = 0; tt < GRP_T; ++tt) {
            // FIX (R7): offset is chalf * 32 floats (channels [32,64) for odd
            // lane). The previous chalf*36 read past the valid 64 floats into
            // unwritten padding and misaligned weights vs channels.
            const ulonglong2* xv =
                (const ulonglong2*)(buf + tt * XROW + chalf * 32);
            u64 a0 = bias_init, a1 = 0ull, a2 = 0ull, a3 = 0ull;
#pragma unroll
            for (int j = 0; j < 8; j += 2) {
                ulonglong2 p = xv[j];          // broadcast LDS.128 (pair-split)
                a0 = fma2(p.x, wq[2 * j],     a0);
                a1 = fma2(p.y, wq[2 * j + 1], a1);
                ulonglong2 q = xv[j + 1];
                a2 = fma2(q.x, wq[2 * j + 2], a2);
                a3 = fma2(q.y, wq[2 * j + 3], a3);
            }
            float2 f = unpack2(add2(add2(a0, a1), add2(a2, a3)));
            float part = f.x + f.y;
            part += __shfl_xor_sync(0xffffffffu, part, 1);
            // LIF: mem = 0.9*mem + cur; spike if mem >= 1; reset to 0
            mem = fmaf(mem, 0.9f, part);
            if (mem >= 1.0f) { cnt += 1.0f; mem = 0.0f; }
        }

        if (g + 2 < NGRP) {
            __syncthreads();                   // everyone done reading buf
            load_group(g + 2, (float*)sbuf[g & 1]);
        }
    }

    if (chalf == 0) counts_out[b * NH + h] = cnt;
}

// ---------------------------------------------------------------------------
// Kernel 2: tda MLP + fused-feature classifier layer 1 (pre-BN h rows)
// ---------------------------------------------------------------------------
__global__ void __launch_bounds__(128) head_kernel(
    const float* __restrict__ tda,
    const float* __restrict__ Wt1, const float* __restrict__ bt1,
    const float* __restrict__ Wt2, const float* __restrict__ bt2,
    const float* __restrict__ Wc1, const float* __restrict__ bc1,
    const float* __restrict__ counts)
{
    __shared__ float s_tda[NTDA];
    __shared__ float s_h1[64];
    __shared__ float s_h2[64];
    __shared__ float s_fr[NH];

    const int b = blockIdx.x, tid = threadIdx.x;

    for (int i = tid; i < NTDA; i += 128) s_tda[i] = tda[b * NTDA + i];
    s_fr[tid] = counts[b * NH + tid] * (1.0f / (float)NT);
    __syncthreads();

    if (tid < 64) {
        float a = bt1[tid];
        const float* w = Wt1 + tid * NTDA;
#pragma unroll 5
        for (int c = 0; c < NTDA; c++) a = fmaf(w[c], s_tda[c], a);
        s_h1[tid] = fmaxf(a, 0.0f);
    }
    __syncthreads();

    if (tid < 64) {
        float a = bt2[tid];
        const float* w = Wt2 + tid * 64;
#pragma unroll 8
        for (int c = 0; c < 64; c++) a = fmaf(w[c], s_h1[c], a);
        s_h2[tid] = fmaxf(a, 0.0f);
    }
    __syncthreads();

    float a = bc1[tid];
    const float* w = Wc1 + tid * (NH + 64);
#pragma unroll 8
    for (int c = 0; c < NH; c++) a = fmaf(w[c], s_fr[c], a);
#pragma unroll 8
    for (int c = 0; c < 64; c++) a = fmaf(w[NH + c], s_h2[c], a);
    g_h[b * NH + tid] = a;
}

// ---------------------------------------------------------------------------
// Kernel 3: BatchNorm batch statistics (two-pass, biased variance)
// ---------------------------------------------------------------------------
__global__ void __launch_bounds__(256) bn_stats_kernel()
{
    const int j = blockIdx.x, tid = threadIdx.x;
    __shared__ float red[256];
    __shared__ float m_sh;

    float v1 = g_h[tid * NH + j];
    float v2 = g_h[(tid + 256) * NH + j];

    red[tid] = v1 + v2;
    __syncthreads();
    for (int o = 128; o > 0; o >>= 1) {
        if (tid < o) red[tid] += red[tid + o];
        __syncthreads();
    }
    if (tid == 0) m_sh = red[0] * (1.0f / (float)NB);
    __syncthreads();

    const float m = m_sh;
    float d1 = v1 - m, d2 = v2 - m;
    red[tid] = d1 * d1 + d2 * d2;
    __syncthreads();
    for (int o = 128; o > 0; o >>= 1) {
        if (tid < o) red[tid] += red[tid + o];
        __syncthreads();
    }
    if (tid == 0) {
        g_mean[j] = m;
        g_rstd[j] = rsqrtf(red[0] * (1.0f / (float)NB) + 1e-5f);
    }
}

// ---------------------------------------------------------------------------
// Kernel 4: BN apply + ReLU + final Linear(128 -> 4)
// ---------------------------------------------------------------------------
__global__ void __launch_bounds__(128) out_kernel(
    const float* __restrict__ gamma, const float* __restrict__ beta,
    const float* __restrict__ Wc2, const float* __restrict__ bc2,
    float* __restrict__ out)
{
    __shared__ float sv[NH];
    const int b = blockIdx.x, tid = threadIdx.x;

    float v = (g_h[b * NH + tid] - g_mean[tid]) * g_rstd[tid] * gamma[tid] + beta[tid];
    sv[tid] = fmaxf(v, 0.0f);
    __syncthreads();

    const int w = tid >> 5, l = tid & 31;
    const float* wr = Wc2 + w * NH;
    float p = sv[l] * wr[l] + sv[l + 32] * wr[l + 32]
            + sv[l + 64] * wr[l + 64] + sv[l + 96] * wr[l + 96];
#pragma unroll
    for (int o = 16; o > 0; o >>= 1) p += __shfl_down_sync(0xffffffffu, p, o);
    if (l == 0) out[b * NCLS + w] = p + bc2[w];
}

// ---------------------------------------------------------------------------
extern "C" void kernel_launch(void* const* d_in, const int* in_sizes, int n_in,
                              void* d_out, int out_size)
{
    const float* x     = (const float*)d_in[0];   // [512,1000,64]
    const float* tda   = (const float*)d_in[1];   // [512,150]
    const float* Wfc   = (const float*)d_in[2];   // [128,64]
    const float* bfc   = (const float*)d_in[3];   // [128]
    const float* Wt1   = (const float*)d_in[4];   // [64,150]
    const float* bt1   = (const float*)d_in[5];   // [64]
    const float* Wt2   = (const float*)d_in[6];   // [64,64]
    const float* bt2   = (const float*)d_in[7];   // [64]
    const float* Wc1   = (const float*)d_in[8];   // [128,192]
    const float* bc1   = (const float*)d_in[9];   // [128]
    const float* gamma = (const float*)d_in[10];  // [128]
    const float* beta  = (const float*)d_in[11];  // [128]
    const float* Wc2   = (const float*)d_in[12];  // [4,128]
    const float* bc2   = (const float*)d_in[13];  // [4]

    float* out    = (float*)d_out;        // first 512*4 = logits
    float* counts = out + NB * NCLS;      // next 512*128 = spike_counts

    snn_kernel<<<NB * 2, 128>>>(x, Wfc, bfc, counts);
    head_kernel<<<NB, 128>>>(tda, Wt1, bt1, Wt2, bt2, Wc1, bc1, counts);
    bn_stats_kernel<<<NH, 256>>>();
    out_kernel<<<NB, 128>>>(gamma, beta, Wc2, bc2, out);
}

// round 10
// speedup vs baseline: 1.3172x; 1.1589x over previous
#include <cuda_runtime.h>

#define NB   512
#define NT   1000
#define NC   64
#define NH   128
#define NTDA 150
#define NCLS 4

#define MT   128                 // GEMM M-tile
#define NBLK (NB * NT / MT)      // 4000 GEMM blocks

// Scratch (no cudaMalloc allowed)
__device__ float g_cur[(size_t)NB * NT * NH];   // currents [B*T, H] (262 MB bss)
__device__ float g_Wd[NC * NH];                 // W^T staged [k][n]
__device__ float g_h[NB * NH];
__device__ float g_mean[NH];
__device__ float g_rstd[NH];

typedef unsigned long long u64;

__device__ __forceinline__ u64 fma2(u64 a, u64 b, u64 c) {
    u64 d;
    asm("fma.rn.f32x2 %0, %1, %2, %3;" : "=l"(d) : "l"(a), "l"(b), "l"(c));
    return d;
}
__device__ __forceinline__ u64 dup2(float v) {
    u64 d;
    asm("mov.b64 %0, {%1, %1};" : "=l"(d) : "f"(v));
    return d;
}
__device__ __forceinline__ void cp16(void* dst_smem, const void* src) {
    unsigned d = (unsigned)__cvta_generic_to_shared(dst_smem);
    asm volatile("cp.async.cg.shared.global [%0], [%1], 16;" :: "r"(d), "l"(src));
}

// ---------------------------------------------------------------------------
// Kernel 0: one-time W transpose  W[n][k] -> g_Wd[k][n]
// ---------------------------------------------------------------------------
__global__ void __launch_bounds__(128) wtr_kernel(const float* __restrict__ Wfc)
{
    const int n = threadIdx.x;
#pragma unroll 8
    for (int k = 0; k < NC; k++) g_Wd[k * NH + n] = Wfc[n * NC + k];
}

// ---------------------------------------------------------------------------
// Kernel 1: currents GEMM.  [MT x 128] tile per block, K=64 full.
// Thread (tm,tn) = (tid/16, tid%16): 8 M-rows x 8 N-cols, N as 4 f32x2 pairs
// at n = 4*tn + {0..3} and 64 + 4*tn + {0..3}. All-broadcast/conflict-free
// smem reads except a 2-way on the A column loads. fma2 pipe is the binder.
// ---------------------------------------------------------------------------
__global__ void __launch_bounds__(256, 2) gemm_kernel(const float* __restrict__ x)
{
    __shared__ __align__(16) float sx[MT * NC];   // 32 KB
    __shared__ __align__(16) float sw[NC * NH];   // 32 KB

    const int tid = threadIdx.x;
    const size_t m0 = (size_t)blockIdx.x * MT;

    // Stage x tile (2048 float4) and W^T (2048 float4), both coalesced.
    const char* xsrc = (const char*)(x + m0 * NC);
#pragma unroll
    for (int r = 0; r < 8; r++) {
        int idx = tid + (r << 8);
        cp16((char*)sx + idx * 16, xsrc + idx * 16);
    }
    const char* wsrc = (const char*)g_Wd;
#pragma unroll
    for (int r = 0; r < 8; r++) {
        int idx = tid + (r << 8);
        cp16((char*)sw + idx * 16, wsrc + idx * 16);
    }
    asm volatile("cp.async.commit_group;");
    asm volatile("cp.async.wait_group 0;");
    __syncthreads();

    const int tm = tid >> 4, tn = tid & 15;
    const float* am = sx + tm * 8 * NC;

    u64 acc[8][4];
#pragma unroll
    for (int mi = 0; mi < 8; mi++)
#pragma unroll
        for (int j = 0; j < 4; j++) acc[mi][j] = 0ull;

    for (int k4 = 0; k4 < 16; k4++) {
        float4 a4[8];
#pragma unroll
        for (int mi = 0; mi < 8; mi++)
            a4[mi] = *(const float4*)(am + mi * NC + k4 * 4);
#pragma unroll
        for (int kk = 0; kk < 4; kk++) {
            const float* brow = sw + (k4 * 4 + kk) * NH + tn * 4;
            ulonglong2 b0 = *(const ulonglong2*)brow;          // n = 4tn..+3
            ulonglong2 b1 = *(const ulonglong2*)(brow + 64);   // n = 64+4tn..+3
#pragma unroll
            for (int mi = 0; mi < 8; mi++) {
                const float* af = (const float*)&a4[mi];
                u64 ad = dup2(af[kk]);
                acc[mi][0] = fma2(ad, b0.x, acc[mi][0]);
                acc[mi][1] = fma2(ad, b0.y, acc[mi][1]);
                acc[mi][2] = fma2(ad, b1.x, acc[mi][2]);
                acc[mi][3] = fma2(ad, b1.y, acc[mi][3]);
            }
        }
    }

    float* crow = g_cur + (m0 + tm * 8) * NH + tn * 4;
#pragma unroll
    for (int mi = 0; mi < 8; mi++) {
        ulonglong2 v0; v0.x = acc[mi][0]; v0.y = acc[mi][1];
        ulonglong2 v1; v1.x = acc[mi][2]; v1.y = acc[mi][3];
        *(ulonglong2*)(crow + mi * NH)      = v0;
        *(ulonglong2*)(crow + mi * NH + 64) = v1;
    }
}

// ---------------------------------------------------------------------------
// Kernel 2: LIF scan.  Thread = (b,h); coalesced LDG over t; bias folded here.
// ---------------------------------------------------------------------------
__global__ void __launch_bounds__(128) scan_kernel(
    const float* __restrict__ bfc, float* __restrict__ counts_out)
{
    const int b = blockIdx.x, h = threadIdx.x;
    const float* cur = g_cur + (size_t)b * NT * NH + h;
    const float bias = bfc[h];

    float mem = 0.0f, cnt = 0.0f;
    for (int tg = 0; tg < NT / 8; tg++) {
        float c[8];
#pragma unroll
        for (int i = 0; i < 8; i++) c[i] = cur[(tg * 8 + i) * NH];
#pragma unroll
        for (int i = 0; i < 8; i++) {
            mem = fmaf(mem, 0.9f, c[i] + bias);
            if (mem >= 1.0f) { cnt += 1.0f; mem = 0.0f; }
        }
    }
    counts_out[b * NH + h] = cnt;
}

// ---------------------------------------------------------------------------
// Kernel 3: tda MLP + fused-feature classifier layer 1 (pre-BN h rows)
// ---------------------------------------------------------------------------
__global__ void __launch_bounds__(128) head_kernel(
    const float* __restrict__ tda,
    const float* __restrict__ Wt1, const float* __restrict__ bt1,
    const float* __restrict__ Wt2, const float* __restrict__ bt2,
    const float* __restrict__ Wc1, const float* __restrict__ bc1,
    const float* __restrict__ counts)
{
    __shared__ float s_tda[NTDA];
    __shared__ float s_h1[64];
    __shared__ float s_h2[64];
    __shared__ float s_fr[NH];

    const int b = blockIdx.x, tid = threadIdx.x;

    for (int i = tid; i < NTDA; i += 128) s_tda[i] = tda[b * NTDA + i];
    s_fr[tid] = counts[b * NH + tid] * (1.0f / (float)NT);
    __syncthreads();

    if (tid < 64) {
        float a = bt1[tid];
        const float* w = Wt1 + tid * NTDA;
#pragma unroll 5
        for (int c = 0; c < NTDA; c++) a = fmaf(w[c], s_tda[c], a);
        s_h1[tid] = fmaxf(a, 0.0f);
    }
    __syncthreads();

    if (tid < 64) {
        float a = bt2[tid];
        const float* w = Wt2 + tid * 64;
#pragma unroll 8
        for (int c = 0; c < 64; c++) a = fmaf(w[c], s_h1[c], a);
        s_h2[tid] = fmaxf(a, 0.0f);
    }
    __syncthreads();

    float a = bc1[tid];
    const float* w = Wc1 + tid * (NH + 64);
#pragma unroll 8
    for (int c = 0; c < NH; c++) a = fmaf(w[c], s_fr[c], a);
#pragma unroll 8
    for (int c = 0; c < 64; c++) a = fmaf(w[NH + c], s_h2[c], a);
    g_h[b * NH + tid] = a;
}

// ---------------------------------------------------------------------------
// Kernel 4: BatchNorm batch statistics (two-pass, biased variance)
// ---------------------------------------------------------------------------
__global__ void __launch_bounds__(256) bn_stats_kernel()
{
    const int j = blockIdx.x, tid = threadIdx.x;
    __shared__ float red[256];
    __shared__ float m_sh;

    float v1 = g_h[tid * NH + j];
    float v2 = g_h[(tid + 256) * NH + j];

    red[tid] = v1 + v2;
    __syncthreads();
    for (int o = 128; o > 0; o >>= 1) {
        if (tid < o) red[tid] += red[tid + o];
        __syncthreads();
    }
    if (tid == 0) m_sh = red[0] * (1.0f / (float)NB);
    __syncthreads();

    const float m = m_sh;
    float d1 = v1 - m, d2 = v2 - m;
    red[tid] = d1 * d1 + d2 * d2;
    __syncthreads();
    for (int o = 128; o > 0; o >>= 1) {
        if (tid < o) red[tid] += red[tid + o];
        __syncthreads();
    }
    if (tid == 0) {
        g_mean[j] = m;
        g_rstd[j] = rsqrtf(red[0] * (1.0f / (float)NB) + 1e-5f);
    }
}

// ---------------------------------------------------------------------------
// Kernel 5: BN apply + ReLU + final Linear(128 -> 4)
// ---------------------------------------------------------------------------
__global__ void __launch_bounds__(128) out_kernel(
    const float* __restrict__ gamma, const float* __restrict__ beta,
    const float* __restrict__ Wc2, const float* __restrict__ bc2,
    float* __restrict__ out)
{
    __shared__ float sv[NH];
    const int b = blockIdx.x, tid = threadIdx.x;

    float v = (g_h[b * NH + tid] - g_mean[tid]) * g_rstd[tid] * gamma[tid] + beta[tid];
    sv[tid] = fmaxf(v, 0.0f);
    __syncthreads();

    const int w = tid >> 5, l = tid & 31;
    const float* wr = Wc2 + w * NH;
    float p = sv[l] * wr[l] + sv[l + 32] * wr[l + 32]
            + sv[l + 64] * wr[l + 64] + sv[l + 96] * wr[l + 96];
#pragma unroll
    for (int o = 16; o > 0; o >>= 1) p += __shfl_down_sync(0xffffffffu, p, o);
    if (l == 0) out[b * NCLS + w] = p + bc2[w];
}

// ---------------------------------------------------------------------------
extern "C" void kernel_launch(void* const* d_in, const int* in_sizes, int n_in,
                              void* d_out, int out_size)
{
    const float* x     = (const float*)d_in[0];   // [512,1000,64]
    const float* tda   = (const float*)d_in[1];   // [512,150]
    const float* Wfc   = (const float*)d_in[2];   // [128,64]
    const float* bfc   = (const float*)d_in[3];   // [128]
    const float* Wt1   = (const float*)d_in[4];   // [64,150]
    const float* bt1   = (const float*)d_in[5];   // [64]
    const float* Wt2   = (const float*)d_in[6];   // [64,64]
    const float* bt2   = (const float*)d_in[7];   // [64]
    const float* Wc1   = (const float*)d_in[8];   // [128,192]
    const float* bc1   = (const float*)d_in[9];   // [128]
    const float* gamma = (const float*)d_in[10];  // [128]
    const float* beta  = (const float*)d_in[11];  // [128]
    const float* Wc2   = (const float*)d_in[12];  // [4,128]
    const float* bc2   = (const float*)d_in[13];  // [4]

    float* out    = (float*)d_out;        // first 512*4 = logits
    float* counts = out + NB * NCLS;      // next 512*128 = spike_counts

    wtr_kernel<<<1, 128>>>(Wfc);
    gemm_kernel<<<NBLK, 256>>>(x);
    scan_kernel<<<NB, 128>>>(bfc, counts);
    head_kernel<<<NB, 128>>>(tda, Wt1, bt1, Wt2, bt2, Wc1, bc1, counts);
    bn_stats_kernel<<<NH, 256>>>();
    out_kernel<<<NB, 128>>>(gamma, beta, Wc2, bc2, out);
}